// round 16
// baseline (speedup 1.0000x reference)
#include <cuda_runtime.h>
#include <cuda_bf16.h>

#define NLAT 46
#define NLON 90
#define CH   256
#define SPX  (NLAT * NLON)   // 4140 spatial points

// Heavy rows: 0, 1, 44, 45 (pole rows + rows containing a full pole circle)
#define HEAVY_BLOCKS (4 * NLON)                 // 360
#define LIGHT_BEG    (2 * NLON)                 // 180
#define LIGHT_END    (44 * NLON)                // 3960
#define LIGHT_BLOCKS ((LIGHT_END - LIGHT_BEG + 7) / 8)   // 473

#define MAXNNZ 4096

// Projection GEMM tiling
#define BM 64
#define BN 128
#define BK 16
#define ST2 20   // smem row stride in uint2 (hi,lo pairs); 4g+t conflict-free

// Scratch
__device__ float g_qc[CH * SPX];       // q channel-major [c][s]
__device__ float g_kc[CH * SPX];       // k channel-major [c][s]
__device__ float g_v [SPX * CH];       // v spatial-major [s][c]
__device__ float g_s [MAXNNZ * NLON];  // scores S[n][wo]
__device__ int   g_off[NLAT + 1];

__device__ __forceinline__ unsigned f2tf(float x) {
    unsigned r;
    asm("cvt.rna.tf32.f32 %0, %1;" : "=r"(r) : "f"(x));
    return r;
}
__device__ __forceinline__ uint2 split_tf(float x) {
    unsigned h = f2tf(x);
    unsigned l = f2tf(x - __uint_as_float(h));
    return make_uint2(h, l);
}

__device__ __forceinline__ void mma_tf32(float c[4], const unsigned a[4],
                                         const unsigned b[2]) {
    asm("mma.sync.aligned.m16n8k8.row.col.f32.tf32.tf32.f32 "
        "{%0,%1,%2,%3}, {%4,%5,%6,%7}, {%8,%9}, {%0,%1,%2,%3};"
        : "+f"(c[0]), "+f"(c[1]), "+f"(c[2]), "+f"(c[3])
        : "r"(a[0]), "r"(a[1]), "r"(a[2]), "r"(a[3]), "r"(b[0]), "r"(b[1]));
}

// ---------------------------------------------------------------------------
// Tensor-core projection GEMM (q,k,v by blockIdx.z), 3xTF32 split.
//   out = W @ X + b ;  X: [CH][SPX], W: [CH][CH] row-major (= B col-major).
// hi/lo tf32 interleaved as uint2 in smem -> every fragment load is LDS.64
// carrying both split operands.  8 warps = 2(M)x4(N), warp tile 32x32:
// per kc 2 A-frags x 4 B-frags, 16 LDS.64 -> 24 MMA.
// q,k written channel-major [c][s]; v spatial-major [s][c].
// Block (0,0,0) also computes segment offsets.
// ---------------------------------------------------------------------------
__global__ void __launch_bounds__(256) proj_kernel(
    const float* __restrict__ qo, const float* __restrict__ ki,
    const float* __restrict__ vi,
    const float* __restrict__ q_w, const float* __restrict__ k_w,
    const float* __restrict__ v_w,
    const float* __restrict__ q_b, const float* __restrict__ k_b,
    const float* __restrict__ v_b,
    const int* __restrict__ row_ids, int nnz)
{
    const int which = blockIdx.z;
    const float* X    = (which == 0) ? qo  : (which == 1) ? ki  : vi;
    const float* W    = (which == 0) ? q_w : (which == 1) ? k_w : v_w;
    const float* bias = (which == 0) ? q_b : (which == 1) ? k_b : v_b;
    float* out        = (which == 0) ? g_qc : (which == 1) ? g_kc : g_v;

    const int tid = threadIdx.x;

    if (which == 0 && blockIdx.x == 0 && blockIdx.y == 0 && tid <= NLAT) {
        int lo = 0, hi = nnz;
        while (lo < hi) {
            int mid = (lo + hi) >> 1;
            if (row_ids[mid] < tid) lo = mid + 1; else hi = mid;
        }
        g_off[tid] = lo;
    }

    __shared__ __align__(16) uint2 Xs[BM * ST2];   // 10.24 KB
    __shared__ __align__(16) uint2 Ws[BN * ST2];   // 20.48 KB

    const int s0 = blockIdx.x * BM;
    const int n0 = blockIdx.y * BN;

    const int warp = tid >> 5;
    const int lane = tid & 31;
    const int wm   = warp & 1;         // M half: rows wm*32..+31
    const int wn   = warp >> 1;        // N quarter: cols wn*32..+31
    const int g    = lane >> 2;        // 0..7
    const int t    = lane & 3;         // 0..3

    // fill-stage indices
    const int xsm = tid & 63;          // X spatial row 0..63
    const int xkb = (tid >> 6) * 4;    // X k base {0,4,8,12}
    const int wnr = tid >> 1;          // W row 0..127
    const int wch = (tid & 1) * 8;     // W k base {0,8}

    float acc[2][4][4] = {};           // [mf][nf][4]

    for (int c0 = 0; c0 < CH; c0 += BK) {
        // --- fill Xs : Xs[sm][k] = split(X[(c0+k)*SPX + s0+sm])
        {
            const int s = s0 + xsm;
            #pragma unroll
            for (int j = 0; j < 4; ++j) {
                float x = (s < SPX) ? X[(c0 + xkb + j) * SPX + s] : 0.0f;
                Xs[xsm * ST2 + xkb + j] = split_tf(x);
            }
        }
        // --- fill Ws : Ws[n][k] = split(W[(n0+n)*CH + c0+k])
        {
            const float4* wp = (const float4*)&W[(n0 + wnr) * CH + c0 + wch];
            float4 wa = wp[0], wb = wp[1];
            float wv[8] = {wa.x, wa.y, wa.z, wa.w, wb.x, wb.y, wb.z, wb.w};
            #pragma unroll
            for (int j = 0; j < 8; ++j)
                Ws[wnr * ST2 + wch + j] = split_tf(wv[j]);
        }
        __syncthreads();

        #pragma unroll
        for (int kc = 0; kc < 2; ++kc) {
            // A fragments (2): rows wm*32 + mf*16 + {g, g+8}, k = kc*8 + {t, t+4}
            unsigned ah[2][4], al[2][4];
            #pragma unroll
            for (int mf = 0; mf < 2; ++mf) {
                const int base = (wm * 32 + mf * 16) * ST2 + kc * 8;
                uint2 x0 = Xs[base + g * ST2 + t];
                uint2 x1 = Xs[base + (g + 8) * ST2 + t];
                uint2 x2 = Xs[base + g * ST2 + t + 4];
                uint2 x3 = Xs[base + (g + 8) * ST2 + t + 4];
                ah[mf][0] = x0.x; ah[mf][1] = x1.x; ah[mf][2] = x2.x; ah[mf][3] = x3.x;
                al[mf][0] = x0.y; al[mf][1] = x1.y; al[mf][2] = x2.y; al[mf][3] = x3.y;
            }
            // B fragments (4) + MMAs
            #pragma unroll
            for (int nf = 0; nf < 4; ++nf) {
                const int base = (wn * 32 + nf * 8) * ST2 + kc * 8;
                uint2 b0 = Ws[base + g * ST2 + t];
                uint2 b1 = Ws[base + g * ST2 + t + 4];
                unsigned bh[2] = {b0.x, b1.x};
                unsigned bl[2] = {b0.y, b1.y};
                #pragma unroll
                for (int mf = 0; mf < 2; ++mf) {
                    mma_tf32(acc[mf][nf], ah[mf], bh);
                    mma_tf32(acc[mf][nf], ah[mf], bl);
                    mma_tf32(acc[mf][nf], al[mf], bh);
                }
            }
        }
        __syncthreads();
    }

    // --- epilogue ---
    #pragma unroll
    for (int mf = 0; mf < 2; ++mf) {
        const int sA = s0 + wm * 32 + mf * 16 + g;
        const int sB = sA + 8;
        #pragma unroll
        for (int nf = 0; nf < 4; ++nf) {
            const int c = n0 + wn * 32 + nf * 8 + 2 * t;
            const float b0 = __ldg(&bias[c]);
            const float b1 = __ldg(&bias[c + 1]);
            float* a = acc[mf][nf];
            if (which == 2) {
                if (sA < SPX)
                    *(float2*)&out[sA * CH + c] = make_float2(a[0] + b0, a[1] + b1);
                if (sB < SPX)
                    *(float2*)&out[sB * CH + c] = make_float2(a[2] + b0, a[3] + b1);
            } else {
                if (sA < SPX) {
                    out[c * SPX + sA]       = a[0] + b0;
                    out[(c + 1) * SPX + sA] = a[1] + b1;
                }
                if (sB < SPX) {
                    out[c * SPX + sB]       = a[2] + b0;
                    out[(c + 1) * SPX + sB] = a[3] + b1;
                }
            }
        }
    }
}

// ---------------------------------------------------------------------------
// Score pass (r11 exact — measured good):
//   S[n][wo] = exp(q[t_n,wo] . k[h_n,(w_n+wo)%NLON]) * quad[h_n]
// One warp per (neighbor n, 32-wide wo block). Lanes span wo -> coalesced.
// ---------------------------------------------------------------------------
__global__ void __launch_bounds__(256) score_kernel(
    const int*   __restrict__ row_ids,
    const int*   __restrict__ col_idx,
    const float* __restrict__ quad,
    int nnz)
{
    const int w    = (int)((blockIdx.x * 256 + threadIdx.x) >> 5);
    const int lane = threadIdx.x & 31;
    const int n    = w / 3;
    const int wb   = w - n * 3;
    if (n >= nnz) return;

    const int t   = __ldg(&row_ids[n]);
    const int ci  = __ldg(&col_idx[n]);
    const int hi  = ci / NLON;
    const int wi0 = ci - hi * NLON;

    const int wo  = wb * 32 + lane;
    const bool act = (wo < NLON);
    const int woc = act ? wo : 0;
    int wi = wi0 + woc;
    if (wi >= NLON) wi -= NLON;

    const float* qp = g_qc + t * NLON + woc;
    const float* kp = g_kc + hi * NLON + wi;

    float p0 = 0.f, p1 = 0.f, p2 = 0.f, p3 = 0.f;
    #pragma unroll 4
    for (int c = 0; c < CH; c += 4) {
        p0 += qp[0 * SPX] * kp[0 * SPX];
        p1 += qp[1 * SPX] * kp[1 * SPX];
        p2 += qp[2 * SPX] * kp[2 * SPX];
        p3 += qp[3 * SPX] * kp[3 * SPX];
        qp += 4 * SPX; kp += 4 * SPX;
    }
    float e = __expf((p0 + p1) + (p2 + p3)) * __ldg(&quad[hi]);
    if (act) g_s[n * NLON + wo] = e;
}

// ---------------------------------------------------------------------------
// Output pass (r11 exact — measured good)
// ---------------------------------------------------------------------------
__device__ __forceinline__ void out_step(
    int n, int wo, int lane,
    const int* __restrict__ col_idx,
    float& d, float4& a0, float4& a1)
{
    int ci = __ldg(&col_idx[n]);
    int hi = ci / NLON;
    int wi = ci - hi * NLON + wo;
    if (wi >= NLON) wi -= NLON;
    int base = (hi * NLON + wi) * CH;

    float e = __ldg(&g_s[n * NLON + wo]);

    const float4* vv = (const float4*)(g_v + base);
    float4 v0 = vv[lane];
    float4 v1 = vv[lane + 32];

    d += e;
    a0.x += e * v0.x;  a0.y += e * v0.y;
    a0.z += e * v0.z;  a0.w += e * v0.w;
    a1.x += e * v1.x;  a1.y += e * v1.y;
    a1.z += e * v1.z;  a1.w += e * v1.w;
}

__global__ void __launch_bounds__(256) attn_out_kernel(
    const int* __restrict__ col_idx,
    float*     __restrict__ out)
{
    __shared__ float smem[2304];   // heavy: [8][256]+[8] | light: [256][9]

    const int warp = threadIdx.x >> 5;
    const int lane = threadIdx.x & 31;

    if (blockIdx.x < HEAVY_BLOCKS) {
        const int bi = blockIdx.x;
        int r = bi / NLON;                             // 0..3
        const int t  = (r < 2) ? r : (NLAT - 4 + r);   // 0,1,44,45
        const int wo = bi - r * NLON;
        const int pos = t * NLON + wo;

        float d = 0.0f;
        float4 a0 = make_float4(0.f, 0.f, 0.f, 0.f);
        float4 a1 = make_float4(0.f, 0.f, 0.f, 0.f);

        const int beg = g_off[t];
        const int end = g_off[t + 1];

        #pragma unroll 2
        for (int n = beg + warp; n < end; n += 8)
            out_step(n, wo, lane, col_idx, d, a0, a1);

        float* sb = smem + warp * 256;
        *(float4*)&sb[lane * 4]       = a0;
        *(float4*)&sb[128 + lane * 4] = a1;
        if (lane == 0) smem[2048 + warp] = d;
        __syncthreads();

        const int c = threadIdx.x;
        float s = 0.0f, dt = 0.0f;
        #pragma unroll
        for (int w = 0; w < 8; ++w) s  += smem[w * 256 + c];
        #pragma unroll
        for (int w = 0; w < 8; ++w) dt += smem[2048 + w];
        out[c * SPX + pos] = s / dt;
    } else {
        const int pos0 = LIGHT_BEG + (blockIdx.x - HEAVY_BLOCKS) * 8;
        const int gw   = pos0 + warp;

        if (gw < LIGHT_END) {
            const int t  = gw / NLON;
            const int wo = gw - t * NLON;

            float d = 0.0f;
            float4 a0 = make_float4(0.f, 0.f, 0.f, 0.f);
            float4 a1 = make_float4(0.f, 0.f, 0.f, 0.f);

            const int beg = g_off[t];
            const int end = g_off[t + 1];

            #pragma unroll 2
            for (int n = beg; n < end; ++n)
                out_step(n, wo, lane, col_idx, d, a0, a1);

            const float inv = 1.0f / d;
            const int c0 = lane * 4;
            smem[(c0 + 0) * 9 + warp] = a0.x * inv;
            smem[(c0 + 1) * 9 + warp] = a0.y * inv;
            smem[(c0 + 2) * 9 + warp] = a0.z * inv;
            smem[(c0 + 3) * 9 + warp] = a0.w * inv;
            smem[(c0 + 128) * 9 + warp] = a1.x * inv;
            smem[(c0 + 129) * 9 + warp] = a1.y * inv;
            smem[(c0 + 130) * 9 + warp] = a1.z * inv;
            smem[(c0 + 131) * 9 + warp] = a1.w * inv;
        }
        __syncthreads();

        const int p  = threadIdx.x & 7;
        const int cb = threadIdx.x >> 3;
        if (pos0 + p < LIGHT_END) {
            #pragma unroll
            for (int j = 0; j < 8; ++j) {
                int c = cb + j * 32;
                out[c * SPX + pos0 + p] = smem[c * 9 + p];
            }
        }
    }
}

// ---------------------------------------------------------------------------
extern "C" void kernel_launch(void* const* d_in, const int* in_sizes, int n_in,
                              void* d_out, int out_size)
{
    const float* qo   = (const float*)d_in[0];
    const float* ki   = (const float*)d_in[1];
    const float* vi   = (const float*)d_in[2];
    const float* q_w  = (const float*)d_in[3];
    const float* k_w  = (const float*)d_in[4];
    const float* v_w  = (const float*)d_in[5];
    const float* q_b  = (const float*)d_in[6];
    const float* k_b  = (const float*)d_in[7];
    const float* v_b  = (const float*)d_in[8];
    const float* quad = (const float*)d_in[9];
    const int* row_ids = (const int*)d_in[10];
    const int* col_idx = (const int*)d_in[11];
    const int nnz = in_sizes[10];

    float* out = (float*)d_out;

    dim3 gg((SPX + BM - 1) / BM, CH / BN, 3);   // (65, 2, 3)
    proj_kernel<<<gg, 256>>>(qo, ki, vi, q_w, k_w, v_w, q_b, k_b, v_b,
                             row_ids, nnz);

    int score_warps = 3 * nnz;
    score_kernel<<<(score_warps + 7) / 8, 256>>>(row_ids, col_idx, quad, nnz);

    attn_out_kernel<<<HEAVY_BLOCKS + LIGHT_BLOCKS, 256>>>(col_idx, out);
}

// round 17
// speedup vs baseline: 1.3682x; 1.3682x over previous
#include <cuda_runtime.h>
#include <cuda_bf16.h>

#define NLAT 46
#define NLON 90
#define CH   256
#define SPX  (NLAT * NLON)   // 4140 spatial points

// Heavy rows: 0, 1, 44, 45 (pole rows + rows containing a full pole circle)
#define HEAVY_BLOCKS (4 * NLON)                 // 360
#define LIGHT_BEG    (2 * NLON)                 // 180
#define LIGHT_END    (44 * NLON)                // 3960
#define LIGHT_BLOCKS ((LIGHT_END - LIGHT_BEG + 7) / 8)   // 473

#define MAXNNZ 4096

// Projection GEMM tiling
#define BM 64
#define BN 128
#define BK 16
#define SA 24    // smem row stride in bf16 units (48B: conflict-free ldmatrix)

// Scratch
__device__ float g_qc[CH * SPX];       // q channel-major [c][s]
__device__ float g_kc[CH * SPX];       // k channel-major [c][s]
__device__ float g_v [SPX * CH];       // v spatial-major [s][c]
__device__ float g_s [MAXNNZ * NLON];  // scores S[n][wo]
__device__ int   g_off[NLAT + 1];

// pack two floats -> bf16x2 (a_low in low half, a_high in high half)
__device__ __forceinline__ unsigned pk2(float a_low, float a_high) {
    unsigned r;
    asm("cvt.rn.bf16x2.f32 %0, %1, %2;" : "=r"(r) : "f"(a_high), "f"(a_low));
    return r;
}
// 2-way bf16 split of two consecutive values -> packed hi-plane + lo-plane
__device__ __forceinline__ void split2(float x0, float x1,
                                       unsigned& h, unsigned& l) {
    float h0 = __bfloat162float(__float2bfloat16(x0));
    float h1 = __bfloat162float(__float2bfloat16(x1));
    h = pk2(h0, h1);
    l = pk2(x0 - h0, x1 - h1);
}

#define LDSM_X4(r, addr)                                                     \
    asm volatile("ldmatrix.sync.aligned.m8n8.x4.shared.b16 "                 \
                 "{%0,%1,%2,%3}, [%4];"                                      \
                 : "=r"((r)[0]), "=r"((r)[1]), "=r"((r)[2]), "=r"((r)[3])    \
                 : "r"(addr))

__device__ __forceinline__ void mma_bf16(float c[4], const unsigned a[4],
                                         const unsigned b[2]) {
    asm("mma.sync.aligned.m16n8k16.row.col.f32.bf16.bf16.f32 "
        "{%0,%1,%2,%3}, {%4,%5,%6,%7}, {%8,%9}, {%0,%1,%2,%3};"
        : "+f"(c[0]), "+f"(c[1]), "+f"(c[2]), "+f"(c[3])
        : "r"(a[0]), "r"(a[1]), "r"(a[2]), "r"(a[3]), "r"(b[0]), "r"(b[1]));
}

// ---------------------------------------------------------------------------
// Tensor-core projection GEMM (q,k,v by blockIdx.z), 2-way bf16 split (3 MMA
// terms: hh + hl + lh), m16n8k16, all fragments via ldmatrix.x4.
//   out = W @ X + b ;  X: [CH][SPX], W: [CH][CH] row-major (= B col-major).
// 8 warps = 2(M)x4(N), warp tile 32x32. Mainloop per warp per BK=16 tile:
// 8 LDSM.x4 + 24 HMMA.  q,k written channel-major [c][s]; v spatial-major.
// Block (0,0,0) also computes segment offsets.
// ---------------------------------------------------------------------------
__global__ void __launch_bounds__(256) proj_kernel(
    const float* __restrict__ qo, const float* __restrict__ ki,
    const float* __restrict__ vi,
    const float* __restrict__ q_w, const float* __restrict__ k_w,
    const float* __restrict__ v_w,
    const float* __restrict__ q_b, const float* __restrict__ k_b,
    const float* __restrict__ v_b,
    const int* __restrict__ row_ids, int nnz)
{
    const int which = blockIdx.z;
    const float* X    = (which == 0) ? qo  : (which == 1) ? ki  : vi;
    const float* W    = (which == 0) ? q_w : (which == 1) ? k_w : v_w;
    const float* bias = (which == 0) ? q_b : (which == 1) ? k_b : v_b;
    float* out        = (which == 0) ? g_qc : (which == 1) ? g_kc : g_v;

    const int tid = threadIdx.x;

    if (which == 0 && blockIdx.x == 0 && blockIdx.y == 0 && tid <= NLAT) {
        int lo = 0, hi = nnz;
        while (lo < hi) {
            int mid = (lo + hi) >> 1;
            if (row_ids[mid] < tid) lo = mid + 1; else hi = mid;
        }
        g_off[tid] = lo;
    }

    __shared__ __align__(16) __nv_bfloat16 XsH[BM * SA];  // 3 KB
    __shared__ __align__(16) __nv_bfloat16 XsL[BM * SA];
    __shared__ __align__(16) __nv_bfloat16 WsH[BN * SA];  // 6 KB
    __shared__ __align__(16) __nv_bfloat16 WsL[BN * SA];

    const int s0 = blockIdx.x * BM;
    const int n0 = blockIdx.y * BN;

    const int warp = tid >> 5;
    const int lane = tid & 31;
    const int wm   = warp & 1;         // M half: rows wm*32..+31
    const int wn   = warp >> 1;        // N quarter: cols wn*32..+31
    const int g    = lane >> 2;        // 0..7
    const int t    = lane & 3;         // 0..3

    // fill-stage indices
    const int xsm = tid & 63;          // X spatial row 0..63
    const int xkb = (tid >> 6) * 4;    // X k base {0,4,8,12}
    const int wnr = tid >> 1;          // W row 0..127
    const int wch = (tid & 1) * 8;     // W k base {0,8}

    // ldmatrix lane addressing (bf16-unit offsets; *2 for bytes)
    const unsigned xbH = (unsigned)__cvta_generic_to_shared(XsH);
    const unsigned xbL = (unsigned)__cvta_generic_to_shared(XsL);
    const unsigned wbH = (unsigned)__cvta_generic_to_shared(WsH);
    const unsigned wbL = (unsigned)__cvta_generic_to_shared(WsL);
    const int arow = wm * 32 + (lane & 15);
    const int acol = (lane >> 4) * 8;
    const unsigned aoff = (unsigned)((arow * SA + acol) * 2);
    const int brow = wn * 32 + ((lane >> 4) << 3) + (lane & 7);
    const int bcol = ((lane >> 3) & 1) * 8;
    const unsigned boff = (unsigned)((brow * SA + bcol) * 2);

    float acc[2][4][4] = {};           // [mf][nf][4]

    for (int c0 = 0; c0 < CH; c0 += BK) {
        // --- fill Xs planes: Xs[sm][k] = split(X[(c0+k)*SPX + s0+sm])
        {
            const int s = s0 + xsm;
            float x0 = 0.f, x1 = 0.f, x2 = 0.f, x3 = 0.f;
            if (s < SPX) {
                x0 = X[(c0 + xkb + 0) * SPX + s];
                x1 = X[(c0 + xkb + 1) * SPX + s];
                x2 = X[(c0 + xkb + 2) * SPX + s];
                x3 = X[(c0 + xkb + 3) * SPX + s];
            }
            unsigned h01, l01, h23, l23;
            split2(x0, x1, h01, l01);
            split2(x2, x3, h23, l23);
            *(uint2*)&XsH[xsm * SA + xkb] = make_uint2(h01, h23);
            *(uint2*)&XsL[xsm * SA + xkb] = make_uint2(l01, l23);
        }
        // --- fill Ws planes: Ws[n][k] = split(W[(n0+n)*CH + c0+k])
        {
            const float4* wp = (const float4*)&W[(n0 + wnr) * CH + c0 + wch];
            float4 wa = wp[0], wb = wp[1];
            unsigned h0, l0, h1, l1, h2, l2, h3, l3;
            split2(wa.x, wa.y, h0, l0);
            split2(wa.z, wa.w, h1, l1);
            split2(wb.x, wb.y, h2, l2);
            split2(wb.z, wb.w, h3, l3);
            *(uint4*)&WsH[wnr * SA + wch] = make_uint4(h0, h1, h2, h3);
            *(uint4*)&WsL[wnr * SA + wch] = make_uint4(l0, l1, l2, l3);
        }
        __syncthreads();

        // --- fragments via ldmatrix
        unsigned ah[2][4], al[2][4];
        LDSM_X4(ah[0], xbH + aoff);
        LDSM_X4(ah[1], xbH + aoff + 16 * SA * 2);
        LDSM_X4(al[0], xbL + aoff);
        LDSM_X4(al[1], xbL + aoff + 16 * SA * 2);

        unsigned bhr[2][4], blr[2][4];  // [pair p][4 regs] -> nf = 2p, 2p+1
        LDSM_X4(bhr[0], wbH + boff);
        LDSM_X4(bhr[1], wbH + boff + 16 * SA * 2);
        LDSM_X4(blr[0], wbL + boff);
        LDSM_X4(blr[1], wbL + boff + 16 * SA * 2);

        // --- 24 MMAs: acc += Ah*Bh + Ah*Bl + Al*Bh
        #pragma unroll
        for (int nf = 0; nf < 4; ++nf) {
            const int p = nf >> 1, q2 = (nf & 1) * 2;
            unsigned bh[2] = {bhr[p][q2], bhr[p][q2 + 1]};
            unsigned bl[2] = {blr[p][q2], blr[p][q2 + 1]};
            #pragma unroll
            for (int mf = 0; mf < 2; ++mf) {
                mma_bf16(acc[mf][nf], ah[mf], bh);
                mma_bf16(acc[mf][nf], ah[mf], bl);
                mma_bf16(acc[mf][nf], al[mf], bh);
            }
        }
        __syncthreads();
    }

    // --- epilogue ---
    #pragma unroll
    for (int mf = 0; mf < 2; ++mf) {
        const int sA = s0 + wm * 32 + mf * 16 + g;
        const int sB = sA + 8;
        #pragma unroll
        for (int nf = 0; nf < 4; ++nf) {
            const int c = n0 + wn * 32 + nf * 8 + 2 * t;
            const float b0 = __ldg(&bias[c]);
            const float b1 = __ldg(&bias[c + 1]);
            float* a = acc[mf][nf];
            if (which == 2) {
                if (sA < SPX)
                    *(float2*)&out[sA * CH + c] = make_float2(a[0] + b0, a[1] + b1);
                if (sB < SPX)
                    *(float2*)&out[sB * CH + c] = make_float2(a[2] + b0, a[3] + b1);
            } else {
                if (sA < SPX) {
                    out[c * SPX + sA]       = a[0] + b0;
                    out[(c + 1) * SPX + sA] = a[1] + b1;
                }
                if (sB < SPX) {
                    out[c * SPX + sB]       = a[2] + b0;
                    out[(c + 1) * SPX + sB] = a[3] + b1;
                }
            }
        }
    }
}

// ---------------------------------------------------------------------------
// Score pass (r11 exact — measured good):
//   S[n][wo] = exp(q[t_n,wo] . k[h_n,(w_n+wo)%NLON]) * quad[h_n]
// One warp per (neighbor n, 32-wide wo block). Lanes span wo -> coalesced.
// ---------------------------------------------------------------------------
__global__ void __launch_bounds__(256) score_kernel(
    const int*   __restrict__ row_ids,
    const int*   __restrict__ col_idx,
    const float* __restrict__ quad,
    int nnz)
{
    const int w    = (int)((blockIdx.x * 256 + threadIdx.x) >> 5);
    const int lane = threadIdx.x & 31;
    const int n    = w / 3;
    const int wb   = w - n * 3;
    if (n >= nnz) return;

    const int t   = __ldg(&row_ids[n]);
    const int ci  = __ldg(&col_idx[n]);
    const int hi  = ci / NLON;
    const int wi0 = ci - hi * NLON;

    const int wo  = wb * 32 + lane;
    const bool act = (wo < NLON);
    const int woc = act ? wo : 0;
    int wi = wi0 + woc;
    if (wi >= NLON) wi -= NLON;

    const float* qp = g_qc + t * NLON + woc;
    const float* kp = g_kc + hi * NLON + wi;

    float p0 = 0.f, p1 = 0.f, p2 = 0.f, p3 = 0.f;
    #pragma unroll 4
    for (int c = 0; c < CH; c += 4) {
        p0 += qp[0 * SPX] * kp[0 * SPX];
        p1 += qp[1 * SPX] * kp[1 * SPX];
        p2 += qp[2 * SPX] * kp[2 * SPX];
        p3 += qp[3 * SPX] * kp[3 * SPX];
        qp += 4 * SPX; kp += 4 * SPX;
    }
    float e = __expf((p0 + p1) + (p2 + p3)) * __ldg(&quad[hi]);
    if (act) g_s[n * NLON + wo] = e;
}

// ---------------------------------------------------------------------------
// Output pass (r11 exact — measured good)
// ---------------------------------------------------------------------------
__device__ __forceinline__ void out_step(
    int n, int wo, int lane,
    const int* __restrict__ col_idx,
    float& d, float4& a0, float4& a1)
{
    int ci = __ldg(&col_idx[n]);
    int hi = ci / NLON;
    int wi = ci - hi * NLON + wo;
    if (wi >= NLON) wi -= NLON;
    int base = (hi * NLON + wi) * CH;

    float e = __ldg(&g_s[n * NLON + wo]);

    const float4* vv = (const float4*)(g_v + base);
    float4 v0 = vv[lane];
    float4 v1 = vv[lane + 32];

    d += e;
    a0.x += e * v0.x;  a0.y += e * v0.y;
    a0.z += e * v0.z;  a0.w += e * v0.w;
    a1.x += e * v1.x;  a1.y += e * v1.y;
    a1.z += e * v1.z;  a1.w += e * v1.w;
}

__global__ void __launch_bounds__(256) attn_out_kernel(
    const int* __restrict__ col_idx,
    float*     __restrict__ out)
{
    __shared__ float smem[2304];   // heavy: [8][256]+[8] | light: [256][9]

    const int warp = threadIdx.x >> 5;
    const int lane = threadIdx.x & 31;

    if (blockIdx.x < HEAVY_BLOCKS) {
        const int bi = blockIdx.x;
        int r = bi / NLON;                             // 0..3
        const int t  = (r < 2) ? r : (NLAT - 4 + r);   // 0,1,44,45
        const int wo = bi - r * NLON;
        const int pos = t * NLON + wo;

        float d = 0.0f;
        float4 a0 = make_float4(0.f, 0.f, 0.f, 0.f);
        float4 a1 = make_float4(0.f, 0.f, 0.f, 0.f);

        const int beg = g_off[t];
        const int end = g_off[t + 1];

        #pragma unroll 2
        for (int n = beg + warp; n < end; n += 8)
            out_step(n, wo, lane, col_idx, d, a0, a1);

        float* sb = smem + warp * 256;
        *(float4*)&sb[lane * 4]       = a0;
        *(float4*)&sb[128 + lane * 4] = a1;
        if (lane == 0) smem[2048 + warp] = d;
        __syncthreads();

        const int c = threadIdx.x;
        float s = 0.0f, dt = 0.0f;
        #pragma unroll
        for (int w = 0; w < 8; ++w) s  += smem[w * 256 + c];
        #pragma unroll
        for (int w = 0; w < 8; ++w) dt += smem[2048 + w];
        out[c * SPX + pos] = s / dt;
    } else {
        const int pos0 = LIGHT_BEG + (blockIdx.x - HEAVY_BLOCKS) * 8;
        const int gw   = pos0 + warp;

        if (gw < LIGHT_END) {
            const int t  = gw / NLON;
            const int wo = gw - t * NLON;

            float d = 0.0f;
            float4 a0 = make_float4(0.f, 0.f, 0.f, 0.f);
            float4 a1 = make_float4(0.f, 0.f, 0.f, 0.f);

            const int beg = g_off[t];
            const int end = g_off[t + 1];

            #pragma unroll 2
            for (int n = beg; n < end; ++n)
                out_step(n, wo, lane, col_idx, d, a0, a1);

            const float inv = 1.0f / d;
            const int c0 = lane * 4;
            smem[(c0 + 0) * 9 + warp] = a0.x * inv;
            smem[(c0 + 1) * 9 + warp] = a0.y * inv;
            smem[(c0 + 2) * 9 + warp] = a0.z * inv;
            smem[(c0 + 3) * 9 + warp] = a0.w * inv;
            smem[(c0 + 128) * 9 + warp] = a1.x * inv;
            smem[(c0 + 129) * 9 + warp] = a1.y * inv;
            smem[(c0 + 130) * 9 + warp] = a1.z * inv;
            smem[(c0 + 131) * 9 + warp] = a1.w * inv;
        }
        __syncthreads();

        const int p  = threadIdx.x & 7;
        const int cb = threadIdx.x >> 3;
        if (pos0 + p < LIGHT_END) {
            #pragma unroll
            for (int j = 0; j < 8; ++j) {
                int c = cb + j * 32;
                out[c * SPX + pos0 + p] = smem[c * 9 + p];
            }
        }
    }
}

// ---------------------------------------------------------------------------
extern "C" void kernel_launch(void* const* d_in, const int* in_sizes, int n_in,
                              void* d_out, int out_size)
{
    const float* qo   = (const float*)d_in[0];
    const float* ki   = (const float*)d_in[1];
    const float* vi   = (const float*)d_in[2];
    const float* q_w  = (const float*)d_in[3];
    const float* k_w  = (const float*)d_in[4];
    const float* v_w  = (const float*)d_in[5];
    const float* q_b  = (const float*)d_in[6];
    const float* k_b  = (const float*)d_in[7];
    const float* v_b  = (const float*)d_in[8];
    const float* quad = (const float*)d_in[9];
    const int* row_ids = (const int*)d_in[10];
    const int* col_idx = (const int*)d_in[11];
    const int nnz = in_sizes[10];

    float* out = (float*)d_out;

    dim3 gg((SPX + BM - 1) / BM, CH / BN, 3);   // (65, 2, 3)
    proj_kernel<<<gg, 256>>>(qo, ki, vi, q_w, k_w, v_w, q_b, k_b, v_b,
                             row_ids, nnz);

    int score_warps = 3 * nnz;
    score_kernel<<<(score_warps + 7) / 8, 256>>>(row_ids, col_idx, quad, nnz);

    attn_out_kernel<<<HEAVY_BLOCKS + LIGHT_BLOCKS, 256>>>(col_idx, out);
}